// round 11
// baseline (speedup 1.0000x reference)
#include <cuda_runtime.h>
#include <math.h>
#include <stdint.h>

#define T_TOK 2048
#define DIM   1024
#define NEXP  8
#define FF    512
#define FSH   1024

#define ASTR 20            // A smem row stride (floats): 16 k + 4 pad
#define BSTR 136           // B smem row stride (floats)
#define A_STAGE (128 * ASTR)   // 2560 floats
#define B_STAGE (16 * BSTR)    // 2176 floats
#define NSTAGE 4
#define SMEM_BYTES ((NSTAGE * (A_STAGE + B_STAGE)) * 4)   // 75776 B

// ---------------- scratch (__device__ globals: allocation-free) ----------------
__device__ int   g_count[NEXP];
__device__ int   g_tok[NEXP][T_TOK];
__device__ int   g_eslot[2][T_TOK];
__device__ float g_ew[2][T_TOK];
__device__ float g_Xr[T_TOK * DIM];         // x pre-rounded to tf32
__device__ float g_G [NEXP * T_TOK * FF];   // routed gate pre-act (compact rows)
__device__ float g_U [NEXP * T_TOK * FF];   // routed up
__device__ float g_H [NEXP * T_TOK * FF];   // routed hidden silu(g)*u (tf32-rounded)
__device__ float g_O [NEXP * T_TOK * DIM];  // routed expert outputs (compact rows)
__device__ float g_Gs[T_TOK * FSH];
__device__ float g_Us[T_TOK * FSH];
__device__ float g_Hs[T_TOK * FSH];         // shared hidden (tf32-rounded)

__device__ __forceinline__ float silu_f(float v) {
    return v / (1.f + __expf(-v));
}

__device__ __forceinline__ uint32_t f2tf32(float f) {
    uint32_t u;
    asm("cvt.rna.tf32.f32 %0, %1;" : "=r"(u) : "f"(f));
    return u;
}

__device__ __forceinline__ void mma_tf32(float4& c, const uint32_t a[4], const uint32_t b[2]) {
    asm volatile(
        "mma.sync.aligned.m16n8k8.row.col.f32.tf32.tf32.f32 "
        "{%0,%1,%2,%3}, {%4,%5,%6,%7}, {%8,%9}, {%0,%1,%2,%3};"
        : "+f"(c.x), "+f"(c.y), "+f"(c.z), "+f"(c.w)
        : "r"(a[0]), "r"(a[1]), "r"(a[2]), "r"(a[3]), "r"(b[0]), "r"(b[1]));
}

__device__ __forceinline__ void cp16(uint32_t saddr, const void* gptr) {
    asm volatile("cp.async.cg.shared.global [%0], [%1], 16;" :: "r"(saddr), "l"(gptr));
}
__device__ __forceinline__ void cp_commit() {
    asm volatile("cp.async.commit_group;");
}
template<int N> __device__ __forceinline__ void cp_wait() {
    asm volatile("cp.async.wait_group %0;" :: "n"(N));
}

// ---------------- init ----------------
__global__ void k_init() {
    if (threadIdx.x < NEXP) g_count[threadIdx.x] = 0;
}

// ---------------- x -> tf32-rounded copy (rounding is idempotent) ----------------
__global__ void k_prep_x(const float* __restrict__ x) {
    const size_t i = ((size_t)blockIdx.x * 256 + threadIdx.x) * 4;
    float4 v = *(const float4*)&x[i];
    v.x = __uint_as_float(f2tf32(v.x));
    v.y = __uint_as_float(f2tf32(v.y));
    v.z = __uint_as_float(f2tf32(v.z));
    v.w = __uint_as_float(f2tf32(v.w));
    *(float4*)&g_Xr[i] = v;
}

// ---------------- router (fp32 exact, reads raw x) ----------------
__global__ void k_router(const float* __restrict__ x, const float* __restrict__ Wr,
                         const float* __restrict__ bias) {
    int t    = blockIdx.x * blockDim.y + threadIdx.y;
    int lane = threadIdx.x;
    const float* xr = x + (size_t)t * DIM;
    float acc[NEXP];
#pragma unroll
    for (int e = 0; e < NEXP; e++) acc[e] = 0.f;
    for (int d = lane; d < DIM; d += 32) {
        float xv = xr[d];
        const float* w = Wr + d * NEXP;
#pragma unroll
        for (int e = 0; e < NEXP; e++) acc[e] += xv * w[e];
    }
#pragma unroll
    for (int o = 16; o > 0; o >>= 1)
#pragma unroll
        for (int e = 0; e < NEXP; e++)
            acc[e] += __shfl_down_sync(0xffffffffu, acc[e], o);
    if (lane == 0) {
        float v[NEXP];
#pragma unroll
        for (int e = 0; e < NEXP; e++) v[e] = acc[e] + bias[e];
        int i0 = 0;
#pragma unroll
        for (int e = 1; e < NEXP; e++) if (v[e] > v[i0]) i0 = e;
        int i1 = (i0 == 0) ? 1 : 0;
#pragma unroll
        for (int e = 0; e < NEXP; e++) if (e != i0 && v[e] > v[i1]) i1 = e;
        float e1    = __expf(v[i1] - v[i0]);
        float denom = 1.f + e1;
        float p0 = 1.f / denom, p1 = e1 / denom;
        int p = atomicAdd(&g_count[i0], 1);
        g_tok[i0][p] = t; g_eslot[0][t] = i0 * T_TOK + p; g_ew[0][t] = p0;
        p = atomicAdd(&g_count[i1], 1);
        g_tok[i1][p] = t; g_eslot[1][t] = i1 * T_TOK + p; g_ew[1][t] = p1;
    }
}

// =====================================================================
// tf32 GEMM, 4-stage cp.async pipeline, ONE __syncthreads per slab.
// 128x128 block tile, BK=16, 8 warps (64x32 warp tile).
// A [M,K] row-major, MUST be pre-rounded to tf32 (fragments load raw bits).
// B [K,N] row-major, rounded at fragment-load time.
// =====================================================================
__device__ __forceinline__ void gemm_core(
    const float* __restrict__ A, const int* __restrict__ rowsA, int lda,
    const float* __restrict__ B, int ldb,
    float* __restrict__ C, int ldc,
    int Mcnt, int K)
{
    const int m0 = blockIdx.y * 128;
    if (m0 >= Mcnt) return;
    const int n0 = blockIdx.x * 128;

    extern __shared__ float smem[];
    float* AsAll = smem;                      // NSTAGE x A_STAGE
    float* BsAll = smem + NSTAGE * A_STAGE;   // NSTAGE x B_STAGE

    const int tid  = threadIdx.x;
    const int lane = tid & 31;
    const int w    = tid >> 5;
    const int wm   = w >> 2;
    const int wn   = w & 3;

    // A loader: row am, 8-float seg
    const int am  = tid >> 1;
    const int seg = tid & 1;
    const int amg = m0 + am;
    const bool aval = (amg < Mcnt);
    const float* Arow = A;
    if (aval) {
        int r = rowsA ? rowsA[amg] : amg;
        Arow = A + (size_t)r * lda + seg * 8;
    }
    // B loader: k-row bk, 8 consecutive n
    const int bk  = tid >> 4;
    const int bnt = tid & 15;
    const float* Bptr = B + (size_t)bk * ldb + n0 + bnt * 8;

    const uint32_t sA0 = (uint32_t)__cvta_generic_to_shared(&AsAll[am * ASTR + seg * 8]);
    const uint32_t sB0 = (uint32_t)__cvta_generic_to_shared(&BsAll[bk * BSTR + bnt * 8]);

    // rows never loaded stay zero across all stages
    if (!aval) {
#pragma unroll
        for (int s = 0; s < NSTAGE; s++)
#pragma unroll
            for (int c = 0; c < 8; c++)
                AsAll[s * A_STAGE + am * ASTR + seg * 8 + c] = 0.f;
    }

    float4 acc[4][4];
#pragma unroll
    for (int i = 0; i < 4; i++)
#pragma unroll
        for (int j = 0; j < 4; j++) acc[i][j] = make_float4(0.f, 0.f, 0.f, 0.f);

    const int fk = lane & 3;
    const int fr = lane >> 2;
    const int nslab = K >> 4;

    // prologue: issue slabs 0..2 into stages 0..2
#pragma unroll
    for (int s = 0; s < 3; s++) {
        if (aval) {
            cp16(sA0 + s * (A_STAGE * 4), Arow + s * 16);
            cp16(sA0 + s * (A_STAGE * 4) + 16, Arow + s * 16 + 4);
        }
        const float* bsrc = Bptr + (size_t)(s * 16) * ldb;
        cp16(sB0 + s * (B_STAGE * 4), bsrc);
        cp16(sB0 + s * (B_STAGE * 4) + 16, bsrc + 4);
        cp_commit();
    }

    for (int it = 0; it < nslab; it++) {
        cp_wait<2>();
        __syncthreads();   // slab 'it' ready; stage (it+3)&3 free (computed at it-1)

        const int pre = it + 3;
        if (pre < nslab) {
            const int st = pre & 3;
            if (aval) {
                cp16(sA0 + st * (A_STAGE * 4), Arow + pre * 16);
                cp16(sA0 + st * (A_STAGE * 4) + 16, Arow + pre * 16 + 4);
            }
            const float* bsrc = Bptr + (size_t)(pre * 16) * ldb;
            cp16(sB0 + st * (B_STAGE * 4), bsrc);
            cp16(sB0 + st * (B_STAGE * 4) + 16, bsrc + 4);
        }
        cp_commit();   // always commit (possibly empty) to keep wait<2> math valid

        const float* Ac = AsAll + (it & 3) * A_STAGE;
        const float* Bc = BsAll + (it & 3) * B_STAGE;
#pragma unroll
        for (int ks = 0; ks < 2; ks++) {
            const int kb = ks * 8 + fk;
            uint32_t a[4][4], b[4][2];
#pragma unroll
            for (int i = 0; i < 4; i++) {
                const int m = wm * 64 + i * 16 + fr;
                a[i][0] = __float_as_uint(Ac[m * ASTR + kb]);
                a[i][1] = __float_as_uint(Ac[(m + 8) * ASTR + kb]);
                a[i][2] = __float_as_uint(Ac[m * ASTR + kb + 4]);
                a[i][3] = __float_as_uint(Ac[(m + 8) * ASTR + kb + 4]);
            }
#pragma unroll
            for (int j = 0; j < 4; j++) {
                const int n = wn * 32 + j * 8 + fr;
                b[j][0] = f2tf32(Bc[kb * BSTR + n]);
                b[j][1] = f2tf32(Bc[(kb + 4) * BSTR + n]);
            }
#pragma unroll
            for (int i = 0; i < 4; i++)
#pragma unroll
                for (int j = 0; j < 4; j++)
                    mma_tf32(acc[i][j], a[i], b[j]);
        }
    }

    // ---- epilogue: plain stores ----
    const int er = lane >> 2;
    const int ec = (lane & 3) * 2;
#pragma unroll
    for (int i = 0; i < 4; i++) {
        const int mg0 = m0 + wm * 64 + i * 16 + er;
        const int mg1 = mg0 + 8;
#pragma unroll
        for (int j = 0; j < 4; j++) {
            const int n = n0 + wn * 32 + j * 8 + ec;
            if (mg0 < Mcnt)
                *(float2*)&C[(size_t)mg0 * ldc + n] = make_float2(acc[i][j].x, acc[i][j].y);
            if (mg1 < Mcnt)
                *(float2*)&C[(size_t)mg1 * ldc + n] = make_float2(acc[i][j].z, acc[i][j].w);
        }
    }
}

// ---------------- GEMM wrappers ----------------
__global__ __launch_bounds__(256, 2)
void k_sh_gateup(const float* __restrict__ Sg, const float* __restrict__ Su) {
    const int mat = blockIdx.z;
    gemm_core(g_Xr, nullptr, DIM, mat ? Su : Sg, FSH,
              mat ? g_Us : g_Gs, FSH, T_TOK, DIM);
}

__global__ __launch_bounds__(256, 2)
void k_sh_down(const float* __restrict__ Sd, float* __restrict__ out) {
    gemm_core(g_Hs, nullptr, FSH, Sd, DIM, out, DIM, T_TOK, FSH);
}

__global__ __launch_bounds__(256, 2)
void k_moe_gateup(const float* __restrict__ Wg, const float* __restrict__ Wu) {
    const int z = blockIdx.z, e = z >> 1, mat = z & 1;
    const float* B = (mat ? Wu : Wg) + (size_t)e * DIM * FF;
    float*       C = (mat ? g_U : g_G) + (size_t)e * T_TOK * FF;
    gemm_core(g_Xr, g_tok[e], DIM, B, FF, C, FF, g_count[e], DIM);
}

__global__ __launch_bounds__(256, 2)
void k_moe_down(const float* __restrict__ Wd) {
    const int e = blockIdx.z;
    gemm_core(g_H + (size_t)e * T_TOK * FF, nullptr, FF,
              Wd + (size_t)e * FF * DIM, DIM,
              g_O + (size_t)e * T_TOK * DIM, DIM, g_count[e], FF);
}

// ---------------- elementwise silu*up -> tf32-rounded H ----------------
__global__ void k_moe_silu() {
    const int e = blockIdx.y;
    const int total = g_count[e] * FF;
    const int idx = (blockIdx.x * 256 + threadIdx.x) * 4;
    if (idx >= total) return;
    const size_t base = (size_t)e * T_TOK * FF + idx;
    float4 g4 = *(const float4*)&g_G[base];
    float4 u4 = *(const float4*)&g_U[base];
    float4 h;
    h.x = __uint_as_float(f2tf32(silu_f(g4.x) * u4.x));
    h.y = __uint_as_float(f2tf32(silu_f(g4.y) * u4.y));
    h.z = __uint_as_float(f2tf32(silu_f(g4.z) * u4.z));
    h.w = __uint_as_float(f2tf32(silu_f(g4.w) * u4.w));
    *(float4*)&g_H[base] = h;
}

__global__ void k_sh_silu() {
    const size_t idx = ((size_t)blockIdx.x * 256 + threadIdx.x) * 4;
    float4 g4 = *(const float4*)&g_Gs[idx];
    float4 u4 = *(const float4*)&g_Us[idx];
    float4 h;
    h.x = __uint_as_float(f2tf32(silu_f(g4.x) * u4.x));
    h.y = __uint_as_float(f2tf32(silu_f(g4.y) * u4.y));
    h.z = __uint_as_float(f2tf32(silu_f(g4.z) * u4.z));
    h.w = __uint_as_float(f2tf32(silu_f(g4.w) * u4.w));
    *(float4*)&g_Hs[idx] = h;
}

// ---------------- final combine: out[t] += w0*O[s0] + w1*O[s1] ----------------
__global__ void k_combine(float* __restrict__ out) {
    const int t = blockIdx.x;
    const int i = threadIdx.x * 4;
    const int   s0 = g_eslot[0][t], s1 = g_eslot[1][t];
    const float w0 = g_ew[0][t],    w1 = g_ew[1][t];
    float4 o = *(float4*)&out[(size_t)t * DIM + i];
    float4 a = *(const float4*)&g_O[(size_t)s0 * DIM + i];
    float4 b = *(const float4*)&g_O[(size_t)s1 * DIM + i];
    o.x += w0 * a.x + w1 * b.x;
    o.y += w0 * a.y + w1 * b.y;
    o.z += w0 * a.z + w1 * b.z;
    o.w += w0 * a.w + w1 * b.w;
    *(float4*)&out[(size_t)t * DIM + i] = o;
}

// ---------------- launch ----------------
extern "C" void kernel_launch(void* const* d_in, const int* in_sizes, int n_in,
                              void* d_out, int out_size) {
    const float* x    = (const float*)d_in[0];
    const float* Wr   = (const float*)d_in[1];
    const float* Wg   = (const float*)d_in[2];
    const float* Wu   = (const float*)d_in[3];
    const float* Wd   = (const float*)d_in[4];
    const float* Sg   = (const float*)d_in[5];
    const float* Su   = (const float*)d_in[6];
    const float* Sd   = (const float*)d_in[7];
    const float* bias = (const float*)d_in[8];
    float* out = (float*)d_out;

    // opt-in to >48KB dynamic smem (cheap, idempotent, not an allocation)
    cudaFuncSetAttribute(k_sh_gateup,  cudaFuncAttributeMaxDynamicSharedMemorySize, SMEM_BYTES);
    cudaFuncSetAttribute(k_sh_down,    cudaFuncAttributeMaxDynamicSharedMemorySize, SMEM_BYTES);
    cudaFuncSetAttribute(k_moe_gateup, cudaFuncAttributeMaxDynamicSharedMemorySize, SMEM_BYTES);
    cudaFuncSetAttribute(k_moe_down,   cudaFuncAttributeMaxDynamicSharedMemorySize, SMEM_BYTES);

    k_init<<<1, 32>>>();
    k_router<<<T_TOK / 8, dim3(32, 8)>>>(x, Wr, bias);
    k_prep_x<<<(T_TOK * DIM) / 1024, 256>>>(x);

    // gate+up projections
    k_sh_gateup <<<dim3(FSH / 128, T_TOK / 128, 2),        256, SMEM_BYTES>>>(Sg, Su);
    k_moe_gateup<<<dim3(FF  / 128, T_TOK / 128, NEXP * 2), 256, SMEM_BYTES>>>(Wg, Wu);

    // elementwise SwiGLU (streaming, once; outputs tf32-rounded)
    k_sh_silu <<<(T_TOK * FSH) / 1024, 256>>>();
    k_moe_silu<<<dim3((T_TOK * FF) / 1024, NEXP), 256>>>();

    // down projections
    k_sh_down <<<dim3(DIM / 128, T_TOK / 128),       256, SMEM_BYTES>>>(Sd, out);
    k_moe_down<<<dim3(DIM / 128, T_TOK / 128, NEXP), 256, SMEM_BYTES>>>(Wd);

    // combine routed outputs into shared-expert output
    k_combine<<<T_TOK, 256>>>(out);
}

// round 13
// speedup vs baseline: 1.0145x; 1.0145x over previous
#include <cuda_runtime.h>
#include <math.h>
#include <stdint.h>

#define T_TOK 2048
#define DIM   1024
#define NEXP  8
#define FF    512
#define FSH   1024

#define ASTR 20            // A smem row stride (floats)
#define BSTR 136           // B smem row stride (floats)

// ---------------- scratch (__device__ globals: allocation-free) ----------------
__device__ int   g_count[NEXP];
__device__ int   g_tok[NEXP][T_TOK];
__device__ int   g_eslot[2][T_TOK];
__device__ float g_ew[2][T_TOK];
__device__ float g_Xr[T_TOK * DIM];         // x pre-rounded to tf32
__device__ float g_G [NEXP * T_TOK * FF];   // routed gate pre-act (compact rows)
__device__ float g_U [NEXP * T_TOK * FF];   // routed up
__device__ float g_H [NEXP * T_TOK * FF];   // routed hidden (tf32-rounded)
__device__ float g_O [NEXP * T_TOK * DIM];  // routed expert outputs (compact rows)
__device__ float g_Gs[T_TOK * FSH];
__device__ float g_Us[T_TOK * FSH];
__device__ float g_Hs[T_TOK * FSH];         // shared hidden (tf32-rounded)

__device__ __forceinline__ float silu_f(float v) {
    return v / (1.f + __expf(-v));
}

__device__ __forceinline__ uint32_t f2tf32(float f) {
    uint32_t u;
    asm("cvt.rna.tf32.f32 %0, %1;" : "=r"(u) : "f"(f));
    return u;
}

__device__ __forceinline__ void mma_tf32(float4& c, const uint32_t a[4], const uint32_t b[2]) {
    asm volatile(
        "mma.sync.aligned.m16n8k8.row.col.f32.tf32.tf32.f32 "
        "{%0,%1,%2,%3}, {%4,%5,%6,%7}, {%8,%9}, {%0,%1,%2,%3};"
        : "+f"(c.x), "+f"(c.y), "+f"(c.z), "+f"(c.w)
        : "r"(a[0]), "r"(a[1]), "r"(a[2]), "r"(a[3]), "r"(b[0]), "r"(b[1]));
}

__device__ __forceinline__ void cp16(uint32_t saddr, const void* gptr) {
    asm volatile("cp.async.cg.shared.global [%0], [%1], 16;" :: "r"(saddr), "l"(gptr));
}
__device__ __forceinline__ void cp_commit() {
    asm volatile("cp.async.commit_group;");
}
template<int N> __device__ __forceinline__ void cp_wait() {
    asm volatile("cp.async.wait_group %0;" :: "n"(N));
}

// ---------------- init ----------------
__global__ void k_init() {
    if (threadIdx.x < NEXP) g_count[threadIdx.x] = 0;
}

// ---------------- x -> tf32-rounded copy ----------------
__global__ void k_prep_x(const float* __restrict__ x) {
    const size_t i = ((size_t)blockIdx.x * 256 + threadIdx.x) * 4;
    float4 v = *(const float4*)&x[i];
    v.x = __uint_as_float(f2tf32(v.x));
    v.y = __uint_as_float(f2tf32(v.y));
    v.z = __uint_as_float(f2tf32(v.z));
    v.w = __uint_as_float(f2tf32(v.w));
    *(float4*)&g_Xr[i] = v;
}

// ---------------- router (fp32 exact, reads raw x) ----------------
__global__ void k_router(const float* __restrict__ x, const float* __restrict__ Wr,
                         const float* __restrict__ bias) {
    int t    = blockIdx.x * blockDim.y + threadIdx.y;
    int lane = threadIdx.x;
    const float* xr = x + (size_t)t * DIM;
    float acc[NEXP];
#pragma unroll
    for (int e = 0; e < NEXP; e++) acc[e] = 0.f;
    for (int d = lane; d < DIM; d += 32) {
        float xv = xr[d];
        const float* w = Wr + d * NEXP;
#pragma unroll
        for (int e = 0; e < NEXP; e++) acc[e] += xv * w[e];
    }
#pragma unroll
    for (int o = 16; o > 0; o >>= 1)
#pragma unroll
        for (int e = 0; e < NEXP; e++)
            acc[e] += __shfl_down_sync(0xffffffffu, acc[e], o);
    if (lane == 0) {
        float v[NEXP];
#pragma unroll
        for (int e = 0; e < NEXP; e++) v[e] = acc[e] + bias[e];
        int i0 = 0;
#pragma unroll
        for (int e = 1; e < NEXP; e++) if (v[e] > v[i0]) i0 = e;
        int i1 = (i0 == 0) ? 1 : 0;
#pragma unroll
        for (int e = 0; e < NEXP; e++) if (e != i0 && v[e] > v[i1]) i1 = e;
        float e1    = __expf(v[i1] - v[i0]);
        float denom = 1.f + e1;
        float p0 = 1.f / denom, p1 = e1 / denom;
        int p = atomicAdd(&g_count[i0], 1);
        g_tok[i0][p] = t; g_eslot[0][t] = i0 * T_TOK + p; g_ew[0][t] = p0;
        p = atomicAdd(&g_count[i1], 1);
        g_tok[i1][p] = t; g_eslot[1][t] = i1 * T_TOK + p; g_ew[1][t] = p1;
    }
}

// =====================================================================
// tf32 GEMM, cp.async 2-stage pipeline (round-10 proven structure).
// 128x128 block tile, BK=16, 8 warps (64x32 warp tile).
// A [M,K] row-major, PRE-ROUNDED to tf32 (fragments load raw bits).
// B [K,N] row-major, rounded at fragment-load time.
// =====================================================================
__device__ __forceinline__ void gemm_core(
    const float* __restrict__ A, const int* __restrict__ rowsA, int lda,
    const float* __restrict__ B, int ldb,
    float* __restrict__ C, int ldc,
    int Mcnt, int K)
{
    const int m0 = blockIdx.y * 128;
    if (m0 >= Mcnt) return;
    const int n0 = blockIdx.x * 128;

    __shared__ __align__(16) float As[2][128 * ASTR];
    __shared__ __align__(16) float Bs[2][16 * BSTR];

    const int tid  = threadIdx.x;
    const int lane = tid & 31;
    const int w    = tid >> 5;
    const int wm   = w >> 2;
    const int wn   = w & 3;

    // A loader: row am, 8-float seg
    const int am  = tid >> 1;
    const int seg = tid & 1;
    const int amg = m0 + am;
    const bool aval = (amg < Mcnt);
    const float* Arow = A;
    if (aval) {
        int r = rowsA ? rowsA[amg] : amg;
        Arow = A + (size_t)r * lda + seg * 8;
    }
    // B loader: k-row bk, 8 consecutive n
    const int bk  = tid >> 4;
    const int bnt = tid & 15;
    const float* Bptr = B + (size_t)bk * ldb + n0 + bnt * 8;

    uint32_t sA[2], sB[2];
    sA[0] = (uint32_t)__cvta_generic_to_shared(&As[0][am * ASTR + seg * 8]);
    sA[1] = (uint32_t)__cvta_generic_to_shared(&As[1][am * ASTR + seg * 8]);
    sB[0] = (uint32_t)__cvta_generic_to_shared(&Bs[0][bk * BSTR + bnt * 8]);
    sB[1] = (uint32_t)__cvta_generic_to_shared(&Bs[1][bk * BSTR + bnt * 8]);

    // rows never loaded stay zero across both stages
    if (!aval) {
#pragma unroll
        for (int s = 0; s < 2; s++)
#pragma unroll
            for (int c = 0; c < 8; c++)
                As[s][am * ASTR + seg * 8 + c] = 0.f;
    }

    float4 acc[4][4];
#pragma unroll
    for (int i = 0; i < 4; i++)
#pragma unroll
        for (int j = 0; j < 4; j++) acc[i][j] = make_float4(0.f, 0.f, 0.f, 0.f);

    const int fk = lane & 3;
    const int fr = lane >> 2;
    const int nslab = K >> 4;

    // prologue: issue slab 0 into stage 0
    if (aval) { cp16(sA[0], Arow); cp16(sA[0] + 16, Arow + 4); }
    cp16(sB[0], Bptr); cp16(sB[0] + 16, Bptr + 4);
    cp_commit();

    for (int it = 0; it < nslab; it++) {
        const int cur = it & 1;
        if (it + 1 < nslab) {
            const int nxt = cur ^ 1;
            const int k1  = (it + 1) * 16;
            if (aval) { cp16(sA[nxt], Arow + k1); cp16(sA[nxt] + 16, Arow + k1 + 4); }
            const float* bsrc = Bptr + (size_t)k1 * ldb;
            cp16(sB[nxt], bsrc); cp16(sB[nxt] + 16, bsrc + 4);
            cp_commit();
            cp_wait<1>();
        } else {
            cp_wait<0>();
        }
        __syncthreads();

        const float* Ac = As[cur];
        const float* Bc = Bs[cur];
#pragma unroll
        for (int ks = 0; ks < 2; ks++) {
            const int kb = ks * 8 + fk;
            uint32_t a[4][4], b[4][2];
#pragma unroll
            for (int i = 0; i < 4; i++) {
                const int m = wm * 64 + i * 16 + fr;
                a[i][0] = __float_as_uint(Ac[m * ASTR + kb]);
                a[i][1] = __float_as_uint(Ac[(m + 8) * ASTR + kb]);
                a[i][2] = __float_as_uint(Ac[m * ASTR + kb + 4]);
                a[i][3] = __float_as_uint(Ac[(m + 8) * ASTR + kb + 4]);
            }
#pragma unroll
            for (int j = 0; j < 4; j++) {
                const int n = wn * 32 + j * 8 + fr;
                b[j][0] = f2tf32(Bc[kb * BSTR + n]);
                b[j][1] = f2tf32(Bc[(kb + 4) * BSTR + n]);
            }
#pragma unroll
            for (int i = 0; i < 4; i++)
#pragma unroll
                for (int j = 0; j < 4; j++)
                    mma_tf32(acc[i][j], a[i], b[j]);
        }
        __syncthreads();
    }

    // ---- epilogue: plain stores ----
    const int er = lane >> 2;
    const int ec = (lane & 3) * 2;
#pragma unroll
    for (int i = 0; i < 4; i++) {
        const int mg0 = m0 + wm * 64 + i * 16 + er;
        const int mg1 = mg0 + 8;
#pragma unroll
        for (int j = 0; j < 4; j++) {
            const int n = n0 + wn * 32 + j * 8 + ec;
            if (mg0 < Mcnt)
                *(float2*)&C[(size_t)mg0 * ldc + n] = make_float2(acc[i][j].x, acc[i][j].y);
            if (mg1 < Mcnt)
                *(float2*)&C[(size_t)mg1 * ldc + n] = make_float2(acc[i][j].z, acc[i][j].w);
        }
    }
}

// ---------------- merged gate+up: z=0,1 shared (mat), z=2..17 routed ----------------
__global__ __launch_bounds__(256, 2)
void k_gateup_all(const float* __restrict__ Sg, const float* __restrict__ Su,
                  const float* __restrict__ Wg, const float* __restrict__ Wu) {
    const int z = blockIdx.z;
    if (z < 2) {
        // shared expert: N = FSH (8 x-blocks)
        gemm_core(g_Xr, nullptr, DIM, z ? Su : Sg, FSH,
                  z ? g_Us : g_Gs, FSH, T_TOK, DIM);
    } else {
        // routed: N = FF (4 x-blocks); extra x-blocks idle out
        if (blockIdx.x >= FF / 128) return;
        const int e = (z - 2) >> 1, mat = (z - 2) & 1;
        const float* B = (mat ? Wu : Wg) + (size_t)e * DIM * FF;
        float*       C = (mat ? g_U : g_G) + (size_t)e * T_TOK * FF;
        gemm_core(g_Xr, g_tok[e], DIM, B, FF, C, FF, g_count[e], DIM);
    }
}

// ---------------- merged down: z=0 shared, z=1..8 routed ----------------
__global__ __launch_bounds__(256, 2)
void k_down_all(const float* __restrict__ Sd, const float* __restrict__ Wd,
                float* __restrict__ out) {
    const int z = blockIdx.z;
    if (z == 0) {
        gemm_core(g_Hs, nullptr, FSH, Sd, DIM, out, DIM, T_TOK, FSH);
    } else {
        const int e = z - 1;
        gemm_core(g_H + (size_t)e * T_TOK * FF, nullptr, FF,
                  Wd + (size_t)e * FF * DIM, DIM,
                  g_O + (size_t)e * T_TOK * DIM, DIM, g_count[e], FF);
    }
}

// ---------------- merged silu: z=0 shared, z=1..8 routed (tf32-rounded out) --------
__global__ void k_silu_all() {
    const int z = blockIdx.z;
    const size_t idx = ((size_t)blockIdx.x * 256 + threadIdx.x) * 4;
    const float *gp, *up; float* hp; size_t total;
    if (z == 0) {
        total = (size_t)T_TOK * FSH;
        gp = g_Gs; up = g_Us; hp = g_Hs;
    } else {
        const int e = z - 1;
        total = (size_t)g_count[e] * FF;
        const size_t off = (size_t)e * T_TOK * FF;
        gp = g_G + off; up = g_U + off; hp = g_H + off;
    }
    if (idx >= total) return;
    float4 g4 = *(const float4*)&gp[idx];
    float4 u4 = *(const float4*)&up[idx];
    float4 h;
    h.x = __uint_as_float(f2tf32(silu_f(g4.x) * u4.x));
    h.y = __uint_as_float(f2tf32(silu_f(g4.y) * u4.y));
    h.z = __uint_as_float(f2tf32(silu_f(g4.z) * u4.z));
    h.w = __uint_as_float(f2tf32(silu_f(g4.w) * u4.w));
    *(float4*)&hp[idx] = h;
}

// ---------------- final combine: out[t] += w0*O[s0] + w1*O[s1] ----------------
__global__ void k_combine(float* __restrict__ out) {
    const int t = blockIdx.x;
    const int i = threadIdx.x * 4;
    const int   s0 = g_eslot[0][t], s1 = g_eslot[1][t];
    const float w0 = g_ew[0][t],    w1 = g_ew[1][t];
    float4 o = *(float4*)&out[(size_t)t * DIM + i];
    float4 a = *(const float4*)&g_O[(size_t)s0 * DIM + i];
    float4 b = *(const float4*)&g_O[(size_t)s1 * DIM + i];
    o.x += w0 * a.x + w1 * b.x;
    o.y += w0 * a.y + w1 * b.y;
    o.z += w0 * a.z + w1 * b.z;
    o.w += w0 * a.w + w1 * b.w;
    *(float4*)&out[(size_t)t * DIM + i] = o;
}

// ---------------- launch ----------------
extern "C" void kernel_launch(void* const* d_in, const int* in_sizes, int n_in,
                              void* d_out, int out_size) {
    const float* x    = (const float*)d_in[0];
    const float* Wr   = (const float*)d_in[1];
    const float* Wg   = (const float*)d_in[2];
    const float* Wu   = (const float*)d_in[3];
    const float* Wd   = (const float*)d_in[4];
    const float* Sg   = (const float*)d_in[5];
    const float* Su   = (const float*)d_in[6];
    const float* Sd   = (const float*)d_in[7];
    const float* bias = (const float*)d_in[8];
    float* out = (float*)d_out;

    k_init<<<1, 32>>>();
    k_prep_x<<<(T_TOK * DIM) / 1024, 256>>>(x);
    k_router<<<T_TOK / 8, dim3(32, 8)>>>(x, Wr, bias);

    // ALL gate+up projections in one launch (wave-packed)
    k_gateup_all<<<dim3(FSH / 128, T_TOK / 128, 2 + NEXP * 2), 256>>>(Sg, Su, Wg, Wu);

    // ALL SwiGLU elementwise in one launch
    k_silu_all<<<dim3((T_TOK * FSH) / 1024, 1, 1 + NEXP), 256>>>();

    // ALL down projections in one launch
    k_down_all<<<dim3(DIM / 128, T_TOK / 128, 1 + NEXP), 256>>>(Sd, Wd, out);

    // combine routed outputs into shared-expert output
    k_combine<<<T_TOK, 256>>>(out);
}